// round 11
// baseline (speedup 1.0000x reference)
#include <cuda_runtime.h>
#include <cuda_bf16.h>
#include <cstdint>

#define BN    8192
#define DIM   128
#define TOPK  128
#define NTH   512
#define NWARP (NTH / 32)
#define WCAP  128
#define ASTR  136
#define NT    64
#define NTRI  (NT * (NT + 1) / 2)   // 2080 triangular tiles

// -------- device scratch --------
__device__ __nv_bfloat16 g_fnb[(size_t)BN * DIM];
__device__ __nv_bfloat16 g_Sb[(size_t)BN * BN];    // bf16 Gram (128 MB)
__device__ unsigned char g_lab[BN];
__device__ float         g_cent[256 * DIM];
__device__ float         g_ssum[BN];
__device__ float         g_partial[BN];

// ============================ helpers ============================
__device__ __forceinline__ uint32_t smem_u32(const void* p) {
    uint32_t a;
    asm("{ .reg .u64 t; cvta.to.shared.u64 t, %1; cvt.u32.u64 %0, t; }" : "=r"(a) : "l"(p));
    return a;
}
__device__ __forceinline__ unsigned pack_bf16x2(float lo, float hi) {
    unsigned r;
    asm("cvt.rn.bf16x2.f32 %0, %1, %2;" : "=r"(r) : "f"(hi), "f"(lo));
    return r;
}
__device__ __forceinline__ void ldmatrix_x4(uint32_t& r0, uint32_t& r1, uint32_t& r2, uint32_t& r3, uint32_t a) {
    asm volatile("ldmatrix.sync.aligned.m8n8.x4.shared.b16 {%0,%1,%2,%3}, [%4];"
                 : "=r"(r0), "=r"(r1), "=r"(r2), "=r"(r3) : "r"(a));
}
__device__ __forceinline__ void mma_bf16(float* d, const uint32_t* a, const uint32_t* b) {
    asm volatile(
        "mma.sync.aligned.m16n8k16.row.col.f32.bf16.bf16.f32 "
        "{%0,%1,%2,%3}, {%4,%5,%6,%7}, {%8,%9}, {%0,%1,%2,%3};"
        : "+f"(d[0]), "+f"(d[1]), "+f"(d[2]), "+f"(d[3])
        : "r"(a[0]), "r"(a[1]), "r"(a[2]), "r"(a[3]), "r"(b[0]), "r"(b[1]));
}

// 16-bit monotone key for bf16; K0 threshold raw bits: value > 0.125
#define K0RAW 0x3E00
__device__ __forceinline__ unsigned fkey16(unsigned x) {
    return (x ^ (0x8000u | (0x7FFFu & (0u - (x >> 15))))) & 0xFFFFu;
}
__device__ __forceinline__ float val16(unsigned k) {
    unsigned b = (k & 0x8000u) ? (k ^ 0x8000u) : ((~k) & 0xFFFFu);
    return __uint_as_float(b << 16);
}
__device__ __forceinline__ float bflo(unsigned x) { return __uint_as_float(x << 16); }
__device__ __forceinline__ float bfhi(unsigned x) { return __uint_as_float(x & 0xFFFF0000u); }

__device__ __forceinline__ void warp_suffix_select(const unsigned* h, int nb, int target,
                                                   int* out_sel, int* out_above, int lane) {
    int ch = nb >> 5;
    int hi = nb - 1 - lane * ch;
    unsigned pc = 0;
    for (int t = 0; t < ch; t++) pc += h[hi - t];
    unsigned inc = pc;
    #pragma unroll
    for (int off = 1; off < 32; off <<= 1) {
        unsigned u = __shfl_up_sync(0xffffffffu, inc, off);
        if (lane >= off) inc += u;
    }
    unsigned exc = inc - pc;
    if (exc < (unsigned)target && inc >= (unsigned)target) {
        unsigned cum = exc;
        for (int t = 0; t < ch; t++) {
            unsigned c = h[hi - t];
            if (cum + c >= (unsigned)target) { *out_sel = hi - t; *out_above = (int)cum; break; }
            cum += c;
        }
    }
}

// ============================ normalize -> bf16 ============================
__global__ void normalize_kernel(const float* __restrict__ feats) {
    int w    = (blockIdx.x * blockDim.x + threadIdx.x) >> 5;
    int lane = threadIdx.x & 31;
    if (w >= BN) return;
    float4 v = ((const float4*)(feats + (size_t)w * DIM))[lane];
    float ss = v.x * v.x + v.y * v.y + v.z * v.z + v.w * v.w;
    #pragma unroll
    for (int o = 16; o; o >>= 1) ss += __shfl_xor_sync(0xffffffffu, ss, o);
    float inv = rsqrtf(ss);
    unsigned* dst = (unsigned*)(g_fnb + (size_t)w * DIM);
    dst[lane * 2 + 0] = pack_bf16x2(v.x * inv, v.y * inv);
    dst[lane * 2 + 1] = pack_bf16x2(v.z * inv, v.w * inv);
}

// ============================ labels -> u8 ============================
__global__ void label_kernel(const unsigned int* __restrict__ words) {
    int tid = threadIdx.x;
    int any = 0;
    for (int i = tid; i < BN / 2; i += blockDim.x) any |= (words[2 * i + 1] != 0u);
    int tot  = __syncthreads_or(any);
    int is64 = (tot == 0);
    for (int i = tid; i < BN; i += blockDim.x)
        g_lab[i] = (unsigned char)(is64 ? words[2 * i] : words[i]);
}

// ============================ class centroids ============================
__global__ void __launch_bounds__(DIM) centroid_kernel() {
    __shared__ unsigned short idx[BN];
    __shared__ int wcnt4[4];

    int l = blockIdx.x, tid = threadIdx.x, lane = tid & 31, w = tid >> 5;
    unsigned char lc = (unsigned char)l;

    int cnt = 0;
    #pragma unroll 4
    for (int k = 0; k < 64; k++) {
        int j = w * 2048 + k * 32 + lane;
        cnt += (g_lab[j] == lc);
    }
    #pragma unroll
    for (int o = 16; o; o >>= 1) cnt += __shfl_xor_sync(0xffffffffu, cnt, o);
    if (lane == 0) wcnt4[w] = cnt;
    __syncthreads();

    int base = 0;
    #pragma unroll
    for (int ww = 0; ww < 4; ww++) if (ww < w) base += wcnt4[ww];
    int total = wcnt4[0] + wcnt4[1] + wcnt4[2] + wcnt4[3];

    int pos = base;
    for (int k = 0; k < 64; k++) {
        int j = w * 2048 + k * 32 + lane;
        bool m = (g_lab[j] == lc);
        unsigned bm = __ballot_sync(0xffffffffu, m);
        if (m) idx[pos + __popc(bm & ((1u << lane) - 1u))] = (unsigned short)j;
        pos += __popc(bm);
    }
    __syncthreads();

    float c = 0.f;
    const unsigned short* F16 = (const unsigned short*)g_fnb;
    for (int t = 0; t < total; t++) {
        int j = idx[t];
        c += __uint_as_float(((unsigned)__ldg(&F16[(size_t)j * DIM + tid])) << 16);
    }
    g_cent[l * DIM + tid] = c;
}

// ============================ per-row same-label sum ============================
__global__ void ssum_kernel() {
    int gw   = (blockIdx.x * blockDim.x + threadIdx.x) >> 5;
    int lane = threadIdx.x & 31;
    if (gw >= BN) return;
    const unsigned* F = (const unsigned*)(g_fnb + (size_t)gw * DIM);
    unsigned char l = g_lab[gw];
    float4 cv = ((const float4*)(g_cent + (size_t)l * DIM))[lane];
    unsigned x0 = F[lane * 2], x1 = F[lane * 2 + 1];
    float f0 = bflo(x0), f1 = bfhi(x0), f2 = bflo(x1), f3 = bfhi(x1);
    float dot = f0 * cv.x + f1 * cv.y + f2 * cv.z + f3 * cv.w;
    float slf = f0 * f0 + f1 * f1 + f2 * f2 + f3 * f3;
    #pragma unroll
    for (int o = 16; o; o >>= 1) {
        dot += __shfl_xor_sync(0xffffffffu, dot, o);
        slf += __shfl_xor_sync(0xffffffffu, slf, o);
    }
    if (lane == 0) g_ssum[gw] = dot - slf;
}

// ============================ bf16 mma.sync symmetric Gram GEMM ============================
// 512 threads, 16 warps in a 4x4 grid, warp tile 32x32 (32 accs/thread) ->
// ~60 regs/thread so 2 CTAs (32 warps) fit per SM.
__global__ void __launch_bounds__(512, 2) gemm_mma_kernel() {
    int rem = blockIdx.x, tm = 0;
    #pragma unroll 1
    while (rem >= NT - tm) { rem -= NT - tm; tm++; }
    int tn = tm + rem;

    extern __shared__ __align__(16) char sm[];
    __nv_bfloat16* Asm = (__nv_bfloat16*)sm;
    __nv_bfloat16* Bsm = (tm == tn) ? Asm : (__nv_bfloat16*)(sm + 128 * ASTR * 2);

    int tid  = threadIdx.x;
    int wid  = tid >> 5, lane = tid & 31;
    int wm   = wid >> 2, wn = wid & 3;     // 4x4 warp grid

    const uint4* F = (const uint4*)g_fnb;
    #pragma unroll
    for (int it = 0; it < 4; it++) {
        int i = tid + it * 512;
        int r = i >> 4, g = i & 15;
        *(uint4*)(Asm + r * ASTR + g * 8) = F[(size_t)(tm * 128 + r) * 16 + g];
    }
    if (tm != tn) {
        #pragma unroll
        for (int it = 0; it < 4; it++) {
            int i = tid + it * 512;
            int r = i >> 4, g = i & 15;
            *(uint4*)(Bsm + r * ASTR + g * 8) = F[(size_t)(tn * 128 + r) * 16 + g];
        }
    }
    __syncthreads();

    float acc[2][4][4];
    #pragma unroll
    for (int i = 0; i < 2; i++)
        #pragma unroll
        for (int j = 0; j < 4; j++)
            #pragma unroll
            for (int c = 0; c < 4; c++) acc[i][j][c] = 0.f;

    // A x4: lanes 0-15 rows m0+lane, k0..7; lanes 16-31 rows m0+(lane&15), k8..15
    uint32_t a_base = smem_u32(Asm) + ((wm * 32 + (lane & 15)) * ASTR + (lane >> 4) * 8) * 2;
    // B x4: mats {n0..7 x k0..7, n0..7 x k8..15, n8..15 x k0..7, n8..15 x k8..15}
    uint32_t b_base = smem_u32(Bsm) + ((wn * 32 + (lane & 7) + ((lane >> 4) << 3)) * ASTR
                                       + ((lane >> 3) & 1) * 8) * 2;

    #pragma unroll 2
    for (int k0 = 0; k0 < DIM; k0 += 16) {
        uint32_t af[2][4], bf[2][4];
        #pragma unroll
        for (int mt = 0; mt < 2; mt++)
            ldmatrix_x4(af[mt][0], af[mt][1], af[mt][2], af[mt][3],
                        a_base + (mt * 16 * ASTR + k0) * 2);
        #pragma unroll
        for (int nt2 = 0; nt2 < 2; nt2++)
            ldmatrix_x4(bf[nt2][0], bf[nt2][1], bf[nt2][2], bf[nt2][3],
                        b_base + (nt2 * 16 * ASTR + k0) * 2);
        #pragma unroll
        for (int mt = 0; mt < 2; mt++)
            #pragma unroll
            for (int nt = 0; nt < 4; nt++)
                mma_bf16(acc[mt][nt], af[mt], &bf[nt >> 1][(nt & 1) * 2]);
    }
    __syncthreads();

    __nv_bfloat16*  stage = (__nv_bfloat16*)sm;
    unsigned short* st2   = (unsigned short*)(sm + 34816);
    bool mir = (tm != tn);

    #pragma unroll
    for (int mt = 0; mt < 2; mt++) {
        int r0 = wm * 32 + mt * 16 + (lane >> 2);
        #pragma unroll
        for (int nt = 0; nt < 4; nt++) {
            int c0 = wn * 32 + nt * 8 + (lane & 3) * 2;
            unsigned p0 = pack_bf16x2(acc[mt][nt][0], acc[mt][nt][1]);
            unsigned p1 = pack_bf16x2(acc[mt][nt][2], acc[mt][nt][3]);
            *(unsigned*)&stage[r0 * ASTR + c0]       = p0;
            *(unsigned*)&stage[(r0 + 8) * ASTR + c0] = p1;
            if (mir) {
                int ra = r0, rb = r0 + 8;
                st2[(c0)     * 128 + (((ra >> 3) ^ (c0 & 15)) * 8)       + (ra & 7)] = (unsigned short)(p0 & 0xFFFF);
                st2[(c0 + 1) * 128 + (((ra >> 3) ^ ((c0 + 1) & 15)) * 8) + (ra & 7)] = (unsigned short)(p0 >> 16);
                st2[(c0)     * 128 + (((rb >> 3) ^ (c0 & 15)) * 8)       + (rb & 7)] = (unsigned short)(p1 & 0xFFFF);
                st2[(c0 + 1) * 128 + (((rb >> 3) ^ ((c0 + 1) & 15)) * 8) + (rb & 7)] = (unsigned short)(p1 >> 16);
            }
        }
    }
    __syncthreads();
    if (!mir && tid < 128) stage[tid * ASTR + tid] = __float2bfloat16(-1e9f);
    __syncthreads();

    #pragma unroll
    for (int it = 0; it < 4; it++) {
        int i = tid + it * 512;
        int row = i >> 4, g = i & 15;
        uint4 v = *(uint4*)&stage[row * ASTR + g * 8];
        ((uint4*)(g_Sb + (size_t)(tm * 128 + row) * BN + tn * 128))[g] = v;
    }
    if (mir) {
        #pragma unroll
        for (int it = 0; it < 4; it++) {
            int i = tid + it * 512;
            int crow = i >> 4, g = i & 15;
            int pg = g ^ (crow & 15);
            uint4 v = *(uint4*)&st2[crow * 128 + pg * 8];
            ((uint4*)(g_Sb + (size_t)(tn * 128 + crow) * BN + tm * 128))[g] = v;
        }
    }
}

// ============================ per-row top-K sum ============================
__global__ void __launch_bounds__(NTH, 3) topk_kernel() {
    __shared__ unsigned       sval[BN / 2];
    __shared__ unsigned short wcand[NWARP][WCAP];
    __shared__ unsigned       hist[256];
    __shared__ int            wcnt[NWARP];
    __shared__ float          wred[NWARP];
    __shared__ int            s_sel, s_above, s_fast;

    int r    = blockIdx.x;
    int tid  = threadIdx.x;
    int lane = tid & 31;
    int w    = tid >> 5;

    const uint4* S4 = (const uint4*)(g_Sb + (size_t)r * BN);
    uint4 va = __ldcs(&S4[tid]);
    uint4 vb = __ldcs(&S4[tid + NTH]);
    ((uint4*)sval)[tid]       = va;
    ((uint4*)sval)[tid + NTH] = vb;
    unsigned vv[8] = {va.x, va.y, va.z, va.w, vb.x, vb.y, vb.z, vb.w};

    unsigned cacc = 0, flags = 0;
    #pragma unroll
    for (int c = 0; c < 8; c++) {
        unsigned m = __vcmpgts2(vv[c], (K0RAW << 16) | K0RAW);
        cacc  += m & 0x00010001u;
        flags |= (m != 0u) << c;
    }
    int cnt = (int)((cacc & 0xFFFFu) + (cacc >> 16));

    int incl = cnt;
    #pragma unroll
    for (int off = 1; off < 32; off <<= 1) {
        int u = __shfl_up_sync(0xffffffffu, incl, off);
        if (lane >= off) incl += u;
    }
    int wtotal = __shfl_sync(0xffffffffu, incl, 31);
    int pos = incl - cnt;
    if (wtotal <= WCAP) {
        unsigned f = flags;
        while (f) {
            int c = __ffs(f) - 1; f &= f - 1;
            unsigned x = vv[c];
            unsigned lo = x & 0xFFFFu, hi = x >> 16;
            if ((int)(short)lo > K0RAW) wcand[w][pos++] = (unsigned short)fkey16(lo);
            if ((int)(short)hi > K0RAW) wcand[w][pos++] = (unsigned short)fkey16(hi);
        }
    }
    if (lane == 31) wcnt[w] = wtotal;
    __syncthreads();

    if (tid < 32) {
        int c = (lane < NWARP) ? wcnt[lane] : 0;
        int mx = c, sum = c;
        #pragma unroll
        for (int off = 16; off; off >>= 1) {
            mx  = max(mx, __shfl_xor_sync(0xffffffffu, mx, off));
            sum += __shfl_xor_sync(0xffffffffu, sum, off);
        }
        if (lane == 0) s_fast = (mx <= WCAP && sum >= TOPK) ? 1 : 0;
    }
    __syncthreads();
    bool fast  = (s_fast != 0);
    int  mycnt = min(wcnt[w], WCAP);

    unsigned pref = 0, pmask = 0;
    int rem = TOPK;
    #pragma unroll
    for (int shift = 8; shift >= 0; shift -= 8) {
        if (tid < 256) hist[tid] = 0;
        __syncthreads();
        if (fast) {
            for (int t = lane; t < mycnt; t += 32) {
                unsigned k = wcand[w][t];
                if ((k & pmask) == pref) atomicAdd(&hist[(k >> shift) & 255u], 1u);
            }
        } else {
            #pragma unroll
            for (int it = 0; it < 8; it++) {
                unsigned x = sval[tid + it * NTH];
                unsigned klo = fkey16(x & 0xFFFFu), khi = fkey16(x >> 16);
                if ((klo & pmask) == pref) atomicAdd(&hist[(klo >> shift) & 255u], 1u);
                if ((khi & pmask) == pref) atomicAdd(&hist[(khi >> shift) & 255u], 1u);
            }
        }
        __syncthreads();
        if (tid < 32) warp_suffix_select(hist, 256, rem, &s_sel, &s_above, lane);
        __syncthreads();
        pref  |= ((unsigned)s_sel) << shift;
        pmask |= 0xFFu << shift;
        rem   -= s_above;
        __syncthreads();
    }

    float tsum = 0.f;
    if (fast) {
        for (int t = lane; t < mycnt; t += 32) {
            unsigned k = wcand[w][t];
            if (k > pref) tsum += val16(k);
        }
    } else {
        #pragma unroll
        for (int it = 0; it < 8; it++) {
            unsigned x = sval[tid + it * NTH];
            unsigned klo = fkey16(x & 0xFFFFu), khi = fkey16(x >> 16);
            if (klo > pref) tsum += val16(klo);
            if (khi > pref) tsum += val16(khi);
        }
    }

    #pragma unroll
    for (int o = 16; o; o >>= 1) tsum += __shfl_xor_sync(0xffffffffu, tsum, o);
    if (lane == 0) wred[w] = tsum;
    __syncthreads();
    if (tid == 0) {
        float At = 0.f;
        #pragma unroll
        for (int ww = 0; ww < NWARP; ww++) At += wred[ww];
        g_partial[r] = At + (float)rem * val16(pref);
    }
}

// ============================ final scalar reduce ============================
__global__ void reduce_kernel(float* __restrict__ out) {
    __shared__ double red[256];
    int tid = threadIdx.x;
    double s = 0.0;
    for (int i = tid; i < BN; i += 256) s += (double)(g_partial[i] - g_ssum[i]);
    red[tid] = s;
    __syncthreads();
    for (int st = 128; st > 0; st >>= 1) {
        if (tid < st) red[tid] += red[tid + st];
        __syncthreads();
    }
    if (tid == 0) out[0] = (float)(red[0] / (double)BN);
}

// ============================ launch ============================
extern "C" void kernel_launch(void* const* d_in, const int* in_sizes, int n_in,
                              void* d_out, int out_size) {
    (void)in_sizes; (void)n_in; (void)out_size;
    const float*        feats = (const float*)d_in[0];
    const unsigned int* labw  = (const unsigned int*)d_in[1];
    float*              out   = (float*)d_out;

    const int smem = 2 * 128 * ASTR * 2;   // 69632 B
    cudaFuncSetAttribute(gemm_mma_kernel, cudaFuncAttributeMaxDynamicSharedMemorySize, smem);

    normalize_kernel<<<BN / 8, 256>>>(feats);
    label_kernel<<<1, 256>>>(labw);
    centroid_kernel<<<256, DIM>>>();
    gemm_mma_kernel<<<NTRI, 512, smem>>>();
    ssum_kernel<<<BN / 8, 256>>>();
    topk_kernel<<<BN, NTH>>>();
    reduce_kernel<<<1, 256>>>(out);
}

// round 12
// speedup vs baseline: 1.0900x; 1.0900x over previous
#include <cuda_runtime.h>
#include <cuda_bf16.h>
#include <cstdint>

#define BN    8192
#define DIM   128
#define TOPK  128
#define NTH   512
#define NWARP (NTH / 32)
#define WCAP  128
#define ASTR  136
#define NT    64
#define NTRI  (NT * (NT + 1) / 2)   // 2080 triangular tiles

// -------- device scratch --------
__device__ __nv_bfloat16 g_fnb[(size_t)BN * DIM];
__device__ __nv_bfloat16 g_Sb[(size_t)BN * BN];    // bf16 Gram (128 MB)
__device__ unsigned char g_lab[BN];
__device__ float         g_cent[256 * DIM];
__device__ float         g_partial[BN];            // topsum - ssum per row

// ============================ helpers ============================
__device__ __forceinline__ uint32_t smem_u32(const void* p) {
    uint32_t a;
    asm("{ .reg .u64 t; cvta.to.shared.u64 t, %1; cvt.u32.u64 %0, t; }" : "=r"(a) : "l"(p));
    return a;
}
__device__ __forceinline__ unsigned pack_bf16x2(float lo, float hi) {
    unsigned r;
    asm("cvt.rn.bf16x2.f32 %0, %1, %2;" : "=r"(r) : "f"(hi), "f"(lo));
    return r;
}
__device__ __forceinline__ void ldmatrix_x4(uint32_t& r0, uint32_t& r1, uint32_t& r2, uint32_t& r3, uint32_t a) {
    asm volatile("ldmatrix.sync.aligned.m8n8.x4.shared.b16 {%0,%1,%2,%3}, [%4];"
                 : "=r"(r0), "=r"(r1), "=r"(r2), "=r"(r3) : "r"(a));
}
__device__ __forceinline__ void ldmatrix_x2(uint32_t& r0, uint32_t& r1, uint32_t a) {
    asm volatile("ldmatrix.sync.aligned.m8n8.x2.shared.b16 {%0,%1}, [%2];"
                 : "=r"(r0), "=r"(r1) : "r"(a));
}
__device__ __forceinline__ void mma_bf16(float* d, const uint32_t* a, const uint32_t* b) {
    asm volatile(
        "mma.sync.aligned.m16n8k16.row.col.f32.bf16.bf16.f32 "
        "{%0,%1,%2,%3}, {%4,%5,%6,%7}, {%8,%9}, {%0,%1,%2,%3};"
        : "+f"(d[0]), "+f"(d[1]), "+f"(d[2]), "+f"(d[3])
        : "r"(a[0]), "r"(a[1]), "r"(a[2]), "r"(a[3]), "r"(b[0]), "r"(b[1]));
}

#define K0RAW 0x3E00
__device__ __forceinline__ unsigned fkey16(unsigned x) {
    return (x ^ (0x8000u | (0x7FFFu & (0u - (x >> 15))))) & 0xFFFFu;
}
__device__ __forceinline__ float val16(unsigned k) {
    unsigned b = (k & 0x8000u) ? (k ^ 0x8000u) : ((~k) & 0xFFFFu);
    return __uint_as_float(b << 16);
}
__device__ __forceinline__ float bflo(unsigned x) { return __uint_as_float(x << 16); }
__device__ __forceinline__ float bfhi(unsigned x) { return __uint_as_float(x & 0xFFFF0000u); }

__device__ __forceinline__ void warp_suffix_select(const unsigned* h, int nb, int target,
                                                   int* out_sel, int* out_above, int lane) {
    int ch = nb >> 5;
    int hi = nb - 1 - lane * ch;
    unsigned pc = 0;
    for (int t = 0; t < ch; t++) pc += h[hi - t];
    unsigned inc = pc;
    #pragma unroll
    for (int off = 1; off < 32; off <<= 1) {
        unsigned u = __shfl_up_sync(0xffffffffu, inc, off);
        if (lane >= off) inc += u;
    }
    unsigned exc = inc - pc;
    if (exc < (unsigned)target && inc >= (unsigned)target) {
        unsigned cum = exc;
        for (int t = 0; t < ch; t++) {
            unsigned c = h[hi - t];
            if (cum + c >= (unsigned)target) { *out_sel = hi - t; *out_above = (int)cum; break; }
            cum += c;
        }
    }
}

// ============================ prep: normalize rows + labels ============================
__global__ void prep_kernel(const float* __restrict__ feats, const unsigned* __restrict__ words) {
    if (blockIdx.x == 1024) {                       // label block
        int tid = threadIdx.x;
        int any = 0;
        for (int i = tid; i < BN / 2; i += blockDim.x) any |= (words[2 * i + 1] != 0u);
        int tot  = __syncthreads_or(any);
        int is64 = (tot == 0);
        for (int i = tid; i < BN; i += blockDim.x)
            g_lab[i] = (unsigned char)(is64 ? words[2 * i] : words[i]);
        return;
    }
    int w    = (blockIdx.x * blockDim.x + threadIdx.x) >> 5;
    int lane = threadIdx.x & 31;
    float4 v = ((const float4*)(feats + (size_t)w * DIM))[lane];
    float ss = v.x * v.x + v.y * v.y + v.z * v.z + v.w * v.w;
    #pragma unroll
    for (int o = 16; o; o >>= 1) ss += __shfl_xor_sync(0xffffffffu, ss, o);
    float inv = rsqrtf(ss);
    unsigned* dst = (unsigned*)(g_fnb + (size_t)w * DIM);
    dst[lane * 2 + 0] = pack_bf16x2(v.x * inv, v.y * inv);
    dst[lane * 2 + 1] = pack_bf16x2(v.z * inv, v.w * inv);
}

// ============================ class centroids (256 threads, ILP-4) ============================
__global__ void __launch_bounds__(256) centroid_kernel() {
    __shared__ unsigned short idx[BN];     // 16 KB
    __shared__ float cpart[2][DIM];
    __shared__ int wcnt8[8];

    int l = blockIdx.x, tid = threadIdx.x, lane = tid & 31, w = tid >> 5;
    unsigned char lc = (unsigned char)l;
    unsigned lw = (unsigned)lc * 0x01010101u;
    const unsigned* LW = (const unsigned*)g_lab;

    // count pass: each warp owns 1024 rows, word loads + vcmpeq4
    int cnt = 0;
    #pragma unroll 4
    for (int k = 0; k < 8; k++) {
        unsigned e = __vcmpeq4(__ldg(&LW[w * 256 + k * 32 + lane]), lw);
        cnt += __popc(e) >> 3;             // e has 0xFF per match
    }
    #pragma unroll
    for (int o = 16; o; o >>= 1) cnt += __shfl_xor_sync(0xffffffffu, cnt, o);
    if (lane == 0) wcnt8[w] = cnt;
    __syncthreads();

    int base = 0;
    #pragma unroll
    for (int ww = 0; ww < 8; ww++) if (ww < w) base += wcnt8[ww];
    int total = 0;
    #pragma unroll
    for (int ww = 0; ww < 8; ww++) total += wcnt8[ww];

    // compact pass (warp-local, ascending j)
    int pos = base;
    for (int k = 0; k < 32; k++) {
        int j = w * 1024 + k * 32 + lane;
        bool m = (g_lab[j] == lc);
        unsigned bm = __ballot_sync(0xffffffffu, m);
        if (m) idx[pos + __popc(bm & ((1u << lane) - 1u))] = (unsigned short)j;
        pos += __popc(bm);
    }
    __syncthreads();

    // sum: half 0 = even members, half 1 = odd members; dim = tid&127; ILP-4
    int half = tid >> 7;
    int d = tid & 127;
    const unsigned short* F16 = (const unsigned short*)g_fnb;
    float c = 0.f;
    int t = half;
    for (; t + 6 < total; t += 8) {
        float a0 = __uint_as_float(((unsigned)__ldg(&F16[(size_t)idx[t]     * DIM + d])) << 16);
        float a1 = __uint_as_float(((unsigned)__ldg(&F16[(size_t)idx[t + 2] * DIM + d])) << 16);
        float a2 = __uint_as_float(((unsigned)__ldg(&F16[(size_t)idx[t + 4] * DIM + d])) << 16);
        float a3 = __uint_as_float(((unsigned)__ldg(&F16[(size_t)idx[t + 6] * DIM + d])) << 16);
        c += a0; c += a1; c += a2; c += a3;
    }
    for (; t < total; t += 2)
        c += __uint_as_float(((unsigned)__ldg(&F16[(size_t)idx[t] * DIM + d])) << 16);
    cpart[half][d] = c;
    __syncthreads();
    if (tid < DIM) g_cent[l * DIM + tid] = cpart[0][tid] + cpart[1][tid];
}

// ============================ bf16 mma.sync symmetric Gram GEMM (R10 best) ============================
__global__ void __launch_bounds__(256, 2) gemm_mma_kernel() {
    int rem = blockIdx.x, tm = 0;
    #pragma unroll 1
    while (rem >= NT - tm) { rem -= NT - tm; tm++; }
    int tn = tm + rem;

    extern __shared__ __align__(16) char sm[];
    __nv_bfloat16* Asm = (__nv_bfloat16*)sm;
    __nv_bfloat16* Bsm = (tm == tn) ? Asm : (__nv_bfloat16*)(sm + 128 * ASTR * 2);

    int tid  = threadIdx.x;
    int wid  = tid >> 5, lane = tid & 31;
    int wm   = wid >> 2, wn = wid & 3;

    const uint4* F = (const uint4*)g_fnb;
    #pragma unroll
    for (int it = 0; it < 8; it++) {
        int i = tid + it * 256;
        int r = i >> 4, g = i & 15;
        *(uint4*)(Asm + r * ASTR + g * 8) = F[(size_t)(tm * 128 + r) * 16 + g];
    }
    if (tm != tn) {
        #pragma unroll
        for (int it = 0; it < 8; it++) {
            int i = tid + it * 256;
            int r = i >> 4, g = i & 15;
            *(uint4*)(Bsm + r * ASTR + g * 8) = F[(size_t)(tn * 128 + r) * 16 + g];
        }
    }
    __syncthreads();

    float acc[4][4][4];
    #pragma unroll
    for (int i = 0; i < 4; i++)
        #pragma unroll
        for (int j = 0; j < 4; j++)
            #pragma unroll
            for (int c = 0; c < 4; c++) acc[i][j][c] = 0.f;

    uint32_t a_base = smem_u32(Asm) + ((wm * 64 + (lane & 15)) * ASTR + (lane >> 4) * 8) * 2;
    uint32_t b_base = smem_u32(Bsm) + ((wn * 32 + (lane & 7)) * ASTR + ((lane >> 3) & 1) * 8) * 2;

    #pragma unroll
    for (int k0 = 0; k0 < DIM; k0 += 16) {
        uint32_t af[4][4], bf[4][2];
        #pragma unroll
        for (int mt = 0; mt < 4; mt++)
            ldmatrix_x4(af[mt][0], af[mt][1], af[mt][2], af[mt][3],
                        a_base + (mt * 16 * ASTR + k0) * 2);
        #pragma unroll
        for (int nt = 0; nt < 4; nt++)
            ldmatrix_x2(bf[nt][0], bf[nt][1],
                        b_base + (nt * 8 * ASTR + k0) * 2);
        #pragma unroll
        for (int mt = 0; mt < 4; mt++)
            #pragma unroll
            for (int nt = 0; nt < 4; nt++)
                mma_bf16(acc[mt][nt], af[mt], bf[nt]);
    }
    __syncthreads();

    __nv_bfloat16*  stage = (__nv_bfloat16*)sm;
    unsigned short* st2   = (unsigned short*)(sm + 34816);
    bool mir = (tm != tn);

    #pragma unroll
    for (int mt = 0; mt < 4; mt++) {
        int r0 = wm * 64 + mt * 16 + (lane >> 2);
        #pragma unroll
        for (int nt = 0; nt < 4; nt++) {
            int c0 = wn * 32 + nt * 8 + (lane & 3) * 2;
            unsigned p0 = pack_bf16x2(acc[mt][nt][0], acc[mt][nt][1]);
            unsigned p1 = pack_bf16x2(acc[mt][nt][2], acc[mt][nt][3]);
            *(unsigned*)&stage[r0 * ASTR + c0]       = p0;
            *(unsigned*)&stage[(r0 + 8) * ASTR + c0] = p1;
            if (mir) {
                int ra = r0, rb = r0 + 8;
                st2[(c0)     * 128 + (((ra >> 3) ^ (c0 & 15)) * 8)       + (ra & 7)] = (unsigned short)(p0 & 0xFFFF);
                st2[(c0 + 1) * 128 + (((ra >> 3) ^ ((c0 + 1) & 15)) * 8) + (ra & 7)] = (unsigned short)(p0 >> 16);
                st2[(c0)     * 128 + (((rb >> 3) ^ (c0 & 15)) * 8)       + (rb & 7)] = (unsigned short)(p1 & 0xFFFF);
                st2[(c0 + 1) * 128 + (((rb >> 3) ^ ((c0 + 1) & 15)) * 8) + (rb & 7)] = (unsigned short)(p1 >> 16);
            }
        }
    }
    __syncthreads();
    if (!mir && tid < 128) stage[tid * ASTR + tid] = __float2bfloat16(-1e9f);
    __syncthreads();

    #pragma unroll
    for (int it = 0; it < 8; it++) {
        int i = tid + it * 256;
        int row = i >> 4, g = i & 15;
        uint4 v = *(uint4*)&stage[row * ASTR + g * 8];
        ((uint4*)(g_Sb + (size_t)(tm * 128 + row) * BN + tn * 128))[g] = v;
    }
    if (mir) {
        #pragma unroll
        for (int it = 0; it < 8; it++) {
            int i = tid + it * 256;
            int crow = i >> 4, g = i & 15;
            int pg = g ^ (crow & 15);
            uint4 v = *(uint4*)&st2[crow * 128 + pg * 8];
            ((uint4*)(g_Sb + (size_t)(tn * 128 + crow) * BN + tm * 128))[g] = v;
        }
    }
}

// ============================ per-row top-K sum + fused same-label sum ============================
__global__ void __launch_bounds__(NTH, 3) topk_kernel() {
    __shared__ unsigned       sval[BN / 2];
    __shared__ unsigned short wcand[NWARP][WCAP];
    __shared__ unsigned       hist[256];
    __shared__ int            wcnt[NWARP];
    __shared__ float          wred[NWARP];
    __shared__ int            s_sel, s_above, s_fast;

    int r    = blockIdx.x;
    int tid  = threadIdx.x;
    int lane = tid & 31;
    int w    = tid >> 5;

    const uint4* S4 = (const uint4*)(g_Sb + (size_t)r * BN);
    uint4 va = __ldcs(&S4[tid]);
    uint4 vb = __ldcs(&S4[tid + NTH]);
    ((uint4*)sval)[tid]       = va;
    ((uint4*)sval)[tid + NTH] = vb;
    unsigned vv[8] = {va.x, va.y, va.z, va.w, vb.x, vb.y, vb.z, vb.w};

    unsigned cacc = 0, flags = 0;
    #pragma unroll
    for (int c = 0; c < 8; c++) {
        unsigned m = __vcmpgts2(vv[c], (K0RAW << 16) | K0RAW);
        cacc  += m & 0x00010001u;
        flags |= (m != 0u) << c;
    }
    int cnt = (int)((cacc & 0xFFFFu) + (cacc >> 16));

    int incl = cnt;
    #pragma unroll
    for (int off = 1; off < 32; off <<= 1) {
        int u = __shfl_up_sync(0xffffffffu, incl, off);
        if (lane >= off) incl += u;
    }
    int wtotal = __shfl_sync(0xffffffffu, incl, 31);
    int pos = incl - cnt;
    if (wtotal <= WCAP) {
        unsigned f = flags;
        while (f) {
            int c = __ffs(f) - 1; f &= f - 1;
            unsigned x = vv[c];
            unsigned lo = x & 0xFFFFu, hi = x >> 16;
            if ((int)(short)lo > K0RAW) wcand[w][pos++] = (unsigned short)fkey16(lo);
            if ((int)(short)hi > K0RAW) wcand[w][pos++] = (unsigned short)fkey16(hi);
        }
    }
    if (lane == 31) wcnt[w] = wtotal;
    __syncthreads();

    if (tid < 32) {
        int c = (lane < NWARP) ? wcnt[lane] : 0;
        int mx = c, sum = c;
        #pragma unroll
        for (int off = 16; off; off >>= 1) {
            mx  = max(mx, __shfl_xor_sync(0xffffffffu, mx, off));
            sum += __shfl_xor_sync(0xffffffffu, sum, off);
        }
        if (lane == 0) s_fast = (mx <= WCAP && sum >= TOPK) ? 1 : 0;
    }
    __syncthreads();
    bool fast  = (s_fast != 0);
    int  mycnt = min(wcnt[w], WCAP);

    unsigned pref = 0, pmask = 0;
    int rem = TOPK;
    #pragma unroll
    for (int shift = 8; shift >= 0; shift -= 8) {
        if (tid < 256) hist[tid] = 0;
        __syncthreads();
        if (fast) {
            for (int t = lane; t < mycnt; t += 32) {
                unsigned k = wcand[w][t];
                if ((k & pmask) == pref) atomicAdd(&hist[(k >> shift) & 255u], 1u);
            }
        } else {
            #pragma unroll
            for (int it = 0; it < 8; it++) {
                unsigned x = sval[tid + it * NTH];
                unsigned klo = fkey16(x & 0xFFFFu), khi = fkey16(x >> 16);
                if ((klo & pmask) == pref) atomicAdd(&hist[(klo >> shift) & 255u], 1u);
                if ((khi & pmask) == pref) atomicAdd(&hist[(khi >> shift) & 255u], 1u);
            }
        }
        __syncthreads();
        if (tid < 32) warp_suffix_select(hist, 256, rem, &s_sel, &s_above, lane);
        __syncthreads();
        pref  |= ((unsigned)s_sel) << shift;
        pmask |= 0xFFu << shift;
        rem   -= s_above;
        __syncthreads();
    }

    float tsum = 0.f;
    if (fast) {
        for (int t = lane; t < mycnt; t += 32) {
            unsigned k = wcand[w][t];
            if (k > pref) tsum += val16(k);
        }
    } else {
        #pragma unroll
        for (int it = 0; it < 8; it++) {
            unsigned x = sval[tid + it * NTH];
            unsigned klo = fkey16(x & 0xFFFFu), khi = fkey16(x >> 16);
            if (klo > pref) tsum += val16(klo);
            if (khi > pref) tsum += val16(khi);
        }
    }

    #pragma unroll
    for (int o = 16; o; o >>= 1) tsum += __shfl_xor_sync(0xffffffffu, tsum, o);
    if (lane == 0) wred[w] = tsum;
    __syncthreads();

    // ---- warp 0: fused same-label sum via centroid dot, then final write ----
    if (w == 0) {
        const unsigned* Fr = (const unsigned*)(g_fnb + (size_t)r * DIM);
        unsigned char l = g_lab[r];
        float4 cv = ((const float4*)(g_cent + (size_t)l * DIM))[lane];
        unsigned x0 = Fr[lane * 2], x1 = Fr[lane * 2 + 1];
        float f0 = bflo(x0), f1 = bfhi(x0), f2 = bflo(x1), f3 = bfhi(x1);
        float dot = f0 * cv.x + f1 * cv.y + f2 * cv.z + f3 * cv.w;
        float slf = f0 * f0 + f1 * f1 + f2 * f2 + f3 * f3;
        #pragma unroll
        for (int o = 16; o; o >>= 1) {
            dot += __shfl_xor_sync(0xffffffffu, dot, o);
            slf += __shfl_xor_sync(0xffffffffu, slf, o);
        }
        if (lane == 0) {
            float At = 0.f;
            #pragma unroll
            for (int ww = 0; ww < NWARP; ww++) At += wred[ww];
            g_partial[r] = At + (float)rem * val16(pref) - (dot - slf);
        }
    }
}

// ============================ final scalar reduce ============================
__global__ void reduce_kernel(float* __restrict__ out) {
    __shared__ double red[256];
    int tid = threadIdx.x;
    double s = 0.0;
    for (int i = tid; i < BN; i += 256) s += (double)g_partial[i];
    red[tid] = s;
    __syncthreads();
    for (int st = 128; st > 0; st >>= 1) {
        if (tid < st) red[tid] += red[tid + st];
        __syncthreads();
    }
    if (tid == 0) out[0] = (float)(red[0] / (double)BN);
}

// ============================ launch ============================
extern "C" void kernel_launch(void* const* d_in, const int* in_sizes, int n_in,
                              void* d_out, int out_size) {
    (void)in_sizes; (void)n_in; (void)out_size;
    const float*    feats = (const float*)d_in[0];
    const unsigned* labw  = (const unsigned*)d_in[1];
    float*          out   = (float*)d_out;

    const int smem = 2 * 128 * ASTR * 2;   // 69632 B
    cudaFuncSetAttribute(gemm_mma_kernel, cudaFuncAttributeMaxDynamicSharedMemorySize, smem);

    prep_kernel<<<1025, 256>>>(feats, labw);
    centroid_kernel<<<256, 256>>>();
    gemm_mma_kernel<<<NTRI, 256, smem>>>();
    topk_kernel<<<BN, NTH>>>();
    reduce_kernel<<<1, 256>>>(out);
}